// round 8
// baseline (speedup 1.0000x reference)
#include <cuda_runtime.h>
#include <math.h>

// ---------------------------------------------------------------------------
// GraphAttention (e3nn-style), receiver-softmax graph attention.
// Round 7: sender-factorized tensor product.
//   Per node n:  B[h, j] = sum_i x_n[i] * W2[h, i, o]   (all 5 CG paths, j<60 K / j<120 V)
//   Per edge:    G[j]    = sum_h hv[h] * B[snd, h, j]   (cheap, 1920/3840 MAC)
//   then combine with spherical harmonics (sh0, shv) and q~ / softmax.
// Edges are processed in CSR-by-sender order (built on device each launch)
// so warps share B[snd] cache lines.
// ---------------------------------------------------------------------------

#define M0 16
#define M1 8
#define Q0 8
#define Q1 4
#define O0 16
#define O1 8
#define HID 32
#define EB 16
#define NODE_DIM 40
#define OUT_DIM 40

#define N_MAX 20000
#define E_MAX 250000

#define BK_J 60     // K-path B columns per h
#define BV_J 120    // V-path B columns per h

// scratch (device globals: the sanctioned allocation-free workaround)
__device__ float g_qts[N_MAX * Q0];
__device__ float g_qtv[N_MAX * Q1 * 3];
__device__ float g_ex[E_MAX];
__device__ float g_z[N_MAX];
__device__ int   g_deg[N_MAX];
__device__ int   g_cur[N_MAX];
__device__ int   g_eord[E_MAX];
// overlaid B buffer: K layout [n][60][32], later V layout [n][120][32]
__device__ __align__(16) float g_B[(size_t)N_MAX * BV_J * 32];

#define INV_SQRT3 0.57735026918962576f
#define INV_SQRT2 0.70710678118654752f
#define INV_SQRT24 0.20412414523193151f
#define INV_SQRT32 0.17677669529663687f
#define INV_SQRT8 0.35355339059327373f
#define CS_FOLD 0.022821773229381923f     // 1/sqrt(24*80)
#define CV_FOLD 0.011410886614690962f     // 1/sqrt(32*3*80)

// ---------------------------------------------------------------------------
// Kernel 1: per-node q-tilde (wdot + norms folded), zero z/out/deg.
// ---------------------------------------------------------------------------
__global__ void q_kernel(const float* __restrict__ node_ft,
                         const float* __restrict__ wqs,
                         const float* __restrict__ wqv,
                         const float* __restrict__ wds,
                         const float* __restrict__ wdv,
                         float* __restrict__ out, int N)
{
    int n = blockIdx.x * blockDim.x + threadIdx.x;
    if (n >= N) return;
    const float* x = node_ft + (size_t)n * NODE_DIM;

    float xs[M0];
#pragma unroll
    for (int i = 0; i < M0; i++) xs[i] = x[i];
    float xv[M1][3];
#pragma unroll
    for (int i = 0; i < M1; i++)
#pragma unroll
        for (int c = 0; c < 3; c++) xv[i][c] = x[M0 + i * 3 + c];

    float qs[Q0];
#pragma unroll
    for (int o = 0; o < Q0; o++) {
        float t = 0.f;
#pragma unroll
        for (int i = 0; i < M0; i++) t += xs[i] * wqs[i * Q0 + o];
        qs[o] = t * 0.25f;
    }
    float qv[Q1][3];
#pragma unroll
    for (int o = 0; o < Q1; o++)
#pragma unroll
        for (int c = 0; c < 3; c++) {
            float t = 0.f;
#pragma unroll
            for (int i = 0; i < M1; i++) t += xv[i][c] * wqv[i * Q1 + o];
            qv[o][c] = t * INV_SQRT8;
        }

#pragma unroll
    for (int j = 0; j < Q0; j++) {
        float t = 0.f;
#pragma unroll
        for (int i = 0; i < Q0; i++) t += qs[i] * wds[i * Q0 + j];
        g_qts[n * Q0 + j] = t * CS_FOLD;
    }
#pragma unroll
    for (int j = 0; j < Q1; j++)
#pragma unroll
        for (int c = 0; c < 3; c++) {
            float t = 0.f;
#pragma unroll
            for (int i = 0; i < Q1; i++) t += qv[i][c] * wdv[i * Q1 + j];
            g_qtv[n * 12 + j * 3 + c] = t * CV_FOLD;
        }

    g_z[n] = 0.f;
    g_deg[n] = 0;
#pragma unroll
    for (int k = 0; k < OUT_DIM; k++) out[(size_t)n * OUT_DIM + k] = 0.f;
}

// ---------------------------------------------------------------------------
// CSR-by-sender construction
// ---------------------------------------------------------------------------
__global__ void hist_kernel(const int* __restrict__ eidx, int E)
{
    int e = blockIdx.x * blockDim.x + threadIdx.x;
    if (e < E) atomicAdd(&g_deg[eidx[e]], 1);
}

__global__ void scan_kernel(int N)
{
    __shared__ int buf[1024];
    __shared__ int carry_s;
    int tid = threadIdx.x;
    if (tid == 0) carry_s = 0;
    __syncthreads();
    for (int base = 0; base < N; base += 1024) {
        int i = base + tid;
        int v = (i < N) ? g_deg[i] : 0;
        buf[tid] = v;
        __syncthreads();
        for (int s = 1; s < 1024; s <<= 1) {
            int t = (tid >= s) ? buf[tid - s] : 0;
            __syncthreads();
            buf[tid] += t;
            __syncthreads();
        }
        int excl = buf[tid] - v + carry_s;
        if (i < N) g_cur[i] = excl;
        int total = buf[1023];
        __syncthreads();
        if (tid == 0) carry_s += total;
        __syncthreads();
    }
}

__global__ void scatter_kernel(const int* __restrict__ eidx, int E)
{
    int e = blockIdx.x * blockDim.x + threadIdx.x;
    if (e < E) {
        int p = atomicAdd(&g_cur[eidx[e]], 1);
        g_eord[p] = e;
    }
}

// ---------------------------------------------------------------------------
// B build kernels. One block per node; entries computed in a read-friendly
// order, written to gmem in [j][h] layout via padded-smem transpose.
// ---------------------------------------------------------------------------
__global__ void __launch_bounds__(256) bk_kernel(const float* __restrict__ node_ft,
                                                 const float* __restrict__ W2, int N)
{
    __shared__ float sx[NODE_DIM];
    __shared__ float Bs[BK_J * 33];
    int n = blockIdx.x;
    int t = threadIdx.x;
    if (t < NODE_DIM) sx[t] = node_ft[(size_t)n * NODE_DIM + t];
    __syncthreads();

    for (int base = 0; base < 32 * BK_J; base += blockDim.x) {
        int idx = base + t;
        if (idx < 32 * BK_J) {
            int h = idx / BK_J, j = idx - h * BK_J;
            const float* w = W2 + h * 320;
            float acc = 0.f;
            if (j < 8) {
                int o = j;
#pragma unroll
                for (int i = 0; i < 16; i++) acc += sx[i] * w[i * 8 + o];
            } else if (j < 32) {
                int r = j - 8; int c = r >> 3, o = r & 7;
#pragma unroll
                for (int i = 0; i < 8; i++) acc += sx[16 + i * 3 + c] * w[128 + i * 8 + o];
                acc *= INV_SQRT3;
            } else if (j < 36) {
                int o = j - 32;
#pragma unroll
                for (int i = 0; i < 16; i++) acc += sx[i] * w[192 + i * 4 + o];
            } else if (j < 48) {
                int r = j - 36; int o = r / 3, c = r - o * 3;
#pragma unroll
                for (int i = 0; i < 8; i++) acc += sx[16 + i * 3 + c] * w[256 + i * 4 + o];
            } else {
                int r = j - 48; int o = r / 3, a = r - o * 3;
#pragma unroll
                for (int i = 0; i < 8; i++) acc += sx[16 + i * 3 + a] * w[288 + i * 4 + o];
                acc *= INV_SQRT2;
            }
            Bs[j * 33 + h] = acc;
        }
    }
    __syncthreads();
    float* B = g_B + (size_t)n * (BK_J * 32);
    for (int m = t; m < BK_J * 32; m += blockDim.x)
        B[m] = Bs[(m >> 5) * 33 + (m & 31)];
}

__global__ void __launch_bounds__(256) bv_kernel(const float* __restrict__ node_ft,
                                                 const float* __restrict__ W2, int N)
{
    __shared__ float sx[NODE_DIM];
    __shared__ float Bs[BV_J * 33];
    int n = blockIdx.x;
    int t = threadIdx.x;
    if (t < NODE_DIM) sx[t] = node_ft[(size_t)n * NODE_DIM + t];
    __syncthreads();

    for (int base = 0; base < 32 * BV_J; base += blockDim.x) {
        int idx = base + t;
        if (idx < 32 * BV_J) {
            int h = idx / BV_J, j = idx - h * BV_J;
            const float* w = W2 + h * 640;
            float acc = 0.f;
            if (j < 16) {
                int o = j;
#pragma unroll
                for (int i = 0; i < 16; i++) acc += sx[i] * w[i * 16 + o];
            } else if (j < 64) {
                int r = j - 16; int c = r >> 4, o = r & 15;
#pragma unroll
                for (int i = 0; i < 8; i++) acc += sx[16 + i * 3 + c] * w[256 + i * 16 + o];
                acc *= INV_SQRT3;
            } else if (j < 72) {
                int o = j - 64;
#pragma unroll
                for (int i = 0; i < 16; i++) acc += sx[i] * w[384 + i * 8 + o];
            } else if (j < 96) {
                int r = j - 72; int o = r / 3, c = r - o * 3;
#pragma unroll
                for (int i = 0; i < 8; i++) acc += sx[16 + i * 3 + c] * w[512 + i * 8 + o];
            } else {
                int r = j - 96; int o = r / 3, a = r - o * 3;
#pragma unroll
                for (int i = 0; i < 8; i++) acc += sx[16 + i * 3 + a] * w[576 + i * 8 + o];
                acc *= INV_SQRT2;
            }
            Bs[j * 33 + h] = acc;
        }
    }
    __syncthreads();
    float* B = g_B + (size_t)n * (BV_J * 32);
    for (int m = t; m < BV_J * 32; m += blockDim.x)
        B[m] = Bs[(m >> 5) * 33 + (m & 31)];
}

// per-edge hidden activations (silu MLP layer-1 + norms folded)
__device__ __forceinline__ void mlp_hidden(const float* __restrict__ edge_sc, int e,
                                           const float* __restrict__ sW1,
                                           float* __restrict__ hk)
{
    float svv[EB];
    const float4* sp = (const float4*)(edge_sc + (size_t)e * EB);
#pragma unroll
    for (int i = 0; i < EB / 4; i++) {
        float4 v = sp[i];
        svv[i * 4 + 0] = v.x; svv[i * 4 + 1] = v.y;
        svv[i * 4 + 2] = v.z; svv[i * 4 + 3] = v.w;
    }
#pragma unroll
    for (int h = 0; h < HID; h++) {
        float t = 0.f;
#pragma unroll
        for (int i = 0; i < EB; i++) t += svv[i] * sW1[i * HID + h];
        t *= 0.25f;
        hk[h] = (t / (1.0f + __expf(-t))) * INV_SQRT32;
    }
}

// G[j] = sum_h hk[h] * B[j][h]  (B row = 32 floats = 8 float4)
#define DOTB(res, j) do {                                                    \
    float a0 = 0.f, a1 = 0.f, a2 = 0.f, a3 = 0.f;                            \
    _Pragma("unroll")                                                        \
    for (int h4 = 0; h4 < 8; h4++) {                                         \
        float4 b = Bp[(j) * 8 + h4];                                         \
        a0 = fmaf(hk[4 * h4 + 0], b.x, a0);                                  \
        a1 = fmaf(hk[4 * h4 + 1], b.y, a1);                                  \
        a2 = fmaf(hk[4 * h4 + 2], b.z, a2);                                  \
        a3 = fmaf(hk[4 * h4 + 3], b.w, a3);                                  \
    }                                                                        \
    res = (a0 + a1) + (a2 + a3);                                             \
} while (0)

// ---------------------------------------------------------------------------
// Pass 1: per-edge (sorted by sender) K contraction + dot + exp + z.
// ---------------------------------------------------------------------------
__global__ void __launch_bounds__(256) pass1_kernel(
    const int* __restrict__ eidx,
    const float* __restrict__ edge_sh,
    const float* __restrict__ edge_sc,
    const float* __restrict__ W1g,
    int E)
{
    __shared__ float sW1[EB * HID];
    for (int i = threadIdx.x; i < EB * HID; i += blockDim.x) sW1[i] = W1g[i];
    __syncthreads();

    int t = blockIdx.x * blockDim.x + threadIdx.x;
    if (t >= E) return;
    int e = g_eord[t];
    int snd = eidx[e];
    int rcv = eidx[E + e];

    float hk[HID];
    mlp_hidden(edge_sc, e, sW1, hk);

    float4 sh = ((const float4*)edge_sh)[e];
    float sh0 = sh.x, shx = sh.y, shy = sh.z, shz = sh.w;

    const float4* Bp = (const float4*)(g_B + (size_t)snd * (BK_J * 32));
    const float* qts = g_qts + (size_t)rcv * Q0;
    const float* qtv = g_qtv + (size_t)rcv * 12;

    float dot = 0.f;
    // scalar outputs: ks[o] = sh0*G1[o] + shv.G2[:,o]
#pragma unroll
    for (int o = 0; o < Q0; o++) {
        float g1, g2x, g2y, g2z;
        DOTB(g1, o);
        DOTB(g2x, 8 + o);
        DOTB(g2y, 16 + o);
        DOTB(g2z, 24 + o);
        float ksv = sh0 * g1 + shx * g2x + shy * g2y + shz * g2z;
        dot += qts[o] * ksv;
    }
    // vector outputs
#pragma unroll
    for (int o = 0; o < Q1; o++) {
        float g3, g40, g41, g42, u0, u1, u2;
        DOTB(g3, 32 + o);
        DOTB(g40, 36 + o * 3 + 0);
        DOTB(g41, 36 + o * 3 + 1);
        DOTB(g42, 36 + o * 3 + 2);
        DOTB(u0, 48 + o * 3 + 0);
        DOTB(u1, 48 + o * 3 + 1);
        DOTB(u2, 48 + o * 3 + 2);
        float k0 = shx * g3 + sh0 * g40 + (u1 * shz - u2 * shy);
        float k1 = shy * g3 + sh0 * g41 + (u2 * shx - u0 * shz);
        float k2 = shz * g3 + sh0 * g42 + (u0 * shy - u1 * shx);
        dot += qtv[o * 3 + 0] * k0 + qtv[o * 3 + 1] * k1 + qtv[o * 3 + 2] * k2;
    }

    float ex = expf(dot);
    g_ex[e] = ex;
    atomicAdd(&g_z[rcv], ex);
}

// ---------------------------------------------------------------------------
// Pass 2: per-edge V contraction + softmax weight + scatter-add.
// ---------------------------------------------------------------------------
__global__ void __launch_bounds__(256) pass2_kernel(
    const int* __restrict__ eidx,
    const float* __restrict__ edge_sh,
    const float* __restrict__ edge_sc,
    const float* __restrict__ W1g,
    float* __restrict__ out,
    int E)
{
    __shared__ float sW1[EB * HID];
    for (int i = threadIdx.x; i < EB * HID; i += blockDim.x) sW1[i] = W1g[i];
    __syncthreads();

    int t = blockIdx.x * blockDim.x + threadIdx.x;
    if (t >= E) return;
    int e = g_eord[t];
    int snd = eidx[e];
    int rcv = eidx[E + e];

    float hk[HID];
    mlp_hidden(edge_sc, e, sW1, hk);

    float4 sh = ((const float4*)edge_sh)[e];
    float sh0 = sh.x, shx = sh.y, shy = sh.z, shz = sh.w;

    const float4* Bp = (const float4*)(g_B + (size_t)snd * (BV_J * 32));

    float a = sqrtf(g_ex[e] / g_z[rcv]);
    float cs = a * INV_SQRT24;
    float cv = a * INV_SQRT32;
    float* op = out + (size_t)rcv * OUT_DIM;

    // scalar outputs: vs[o] = sh0*G1[o] + shv.G2[:,o]
#pragma unroll
    for (int o = 0; o < O0; o++) {
        float g1, g2x, g2y, g2z;
        DOTB(g1, o);
        DOTB(g2x, 16 + o);
        DOTB(g2y, 32 + o);
        DOTB(g2z, 48 + o);
        float v = sh0 * g1 + shx * g2x + shy * g2y + shz * g2z;
        atomicAdd(op + o, cs * v);
    }
    // vector outputs
#pragma unroll
    for (int o = 0; o < O1; o++) {
        float g3, g40, g41, g42, u0, u1, u2;
        DOTB(g3, 64 + o);
        DOTB(g40, 72 + o * 3 + 0);
        DOTB(g41, 72 + o * 3 + 1);
        DOTB(g42, 72 + o * 3 + 2);
        DOTB(u0, 96 + o * 3 + 0);
        DOTB(u1, 96 + o * 3 + 1);
        DOTB(u2, 96 + o * 3 + 2);
        float v0 = shx * g3 + sh0 * g40 + (u1 * shz - u2 * shy);
        float v1 = shy * g3 + sh0 * g41 + (u2 * shx - u0 * shz);
        float v2 = shz * g3 + sh0 * g42 + (u0 * shy - u1 * shx);
        atomicAdd(op + O0 + o * 3 + 0, cv * v0);
        atomicAdd(op + O0 + o * 3 + 1, cv * v1);
        atomicAdd(op + O0 + o * 3 + 2, cv * v2);
    }
}

// ---------------------------------------------------------------------------
extern "C" void kernel_launch(void* const* d_in, const int* in_sizes, int n_in,
                              void* d_out, int out_size)
{
    const float* node_ft = (const float*)d_in[0];
    const int* eidx      = (const int*)d_in[1];
    const float* edge_sh = (const float*)d_in[2];
    const float* edge_sc = (const float*)d_in[3];
    const float* wqs     = (const float*)d_in[4];
    const float* wqv     = (const float*)d_in[5];
    const float* fck_w1  = (const float*)d_in[6];
    const float* fck_w2  = (const float*)d_in[7];
    const float* fcv_w1  = (const float*)d_in[8];
    const float* fcv_w2  = (const float*)d_in[9];
    const float* wds     = (const float*)d_in[10];
    const float* wdv     = (const float*)d_in[11];
    float* out = (float*)d_out;

    int N = in_sizes[0] / NODE_DIM;
    int E = in_sizes[1] / 2;

    q_kernel<<<(N + 63) / 64, 64>>>(node_ft, wqs, wqv, wds, wdv, out, N);
    hist_kernel<<<(E + 255) / 256, 256>>>(eidx, E);
    scan_kernel<<<1, 1024>>>(N);
    scatter_kernel<<<(E + 255) / 256, 256>>>(eidx, E);

    bk_kernel<<<N, 256>>>(node_ft, fck_w2, N);
    pass1_kernel<<<(E + 255) / 256, 256>>>(eidx, edge_sh, edge_sc, fck_w1, E);

    bv_kernel<<<N, 256>>>(node_ft, fcv_w2, N);
    pass2_kernel<<<(E + 255) / 256, 256>>>(eidx, edge_sh, edge_sc, fcv_w1, out, E);
}

// round 9
// speedup vs baseline: 2.0411x; 2.0411x over previous
#include <cuda_runtime.h>
#include <math.h>

// ---------------------------------------------------------------------------
// GraphAttention (e3nn-style) — round-6 structure (broadcast-smem weight
// streaming, per-edge threads) with fp32x2 packed FFMA (sm_103a FFMA2).
// Inputs (metadata order):
//  0 node_ft[N,40] 1 edge_index[2,E](int32) 2 edge_sh[E,4] 3 edge_scalars[E,16]
//  4 w_q_s[16,8] 5 w_q_v[8,4] 6 fck_w1[16,32] 7 fck_w2[32,320]
//  8 fcv_w1[16,32] 9 fcv_w2[32,640] 10 wdot_s[8,8] 11 wdot_v[4,4]
// Output: [N,40] f32
// ---------------------------------------------------------------------------

#define M0 16
#define M1 8
#define Q0 8
#define Q1 4
#define O0 16
#define O1 8
#define HID 32
#define EB 16
#define TPK 320
#define TPV 640
#define NODE_DIM 40
#define OUT_DIM 40

#define N_MAX 20000
#define E_MAX 250000

__device__ float g_qts[N_MAX * Q0];
__device__ float g_qtv[N_MAX * Q1 * 3];
__device__ float g_ex[E_MAX];
__device__ float g_z[N_MAX];

#define INV_SQRT3 0.57735026918962576f
#define INV_SQRT2 0.70710678118654752f
#define INV_SQRT24 0.20412414523193151f
#define INV_SQRT32 0.17677669529663687f
#define INV_SQRT8 0.35355339059327373f
#define CS_FOLD 0.022821773229381923f     // 1/sqrt(24*80)
#define CV_FOLD 0.011410886614690962f     // 1/sqrt(32*3*80)

typedef unsigned long long u64;

__device__ __forceinline__ u64 pk(float x, float y) {
    u64 r; asm("mov.b64 %0, {%1, %2};" : "=l"(r) : "f"(x), "f"(y)); return r;
}
__device__ __forceinline__ void upk(u64 v, float& x, float& y) {
    asm("mov.b64 {%0, %1}, %2;" : "=f"(x), "=f"(y) : "l"(v));
}
__device__ __forceinline__ u64 fma2(u64 a, u64 b, u64 c) {
    u64 d; asm("fma.rn.f32x2 %0, %1, %2, %3;" : "=l"(d) : "l"(a), "l"(b), "l"(c));
    return d;
}

// w2[j] (+)= sum_h hkp[h] * W2pair[h, j]   (packed over output channel o)
// ROW2 = row stride of W2 in u64 units; NP = number of packed pairs per slice.
template<int ROW2, int NP>
__device__ __forceinline__ void weff2(const float* __restrict__ base,
                                      const u64* __restrict__ hkp,
                                      u64* __restrict__ w)
{
#pragma unroll
    for (int j = 0; j < NP; j++) w[j] = 0ull;
    const u64* b = (const u64*)base;
#pragma unroll
    for (int h = 0; h < HID; h++) {
        u64 c = hkp[h];
#pragma unroll
        for (int j = 0; j < NP; j++)
            w[j] = fma2(c, b[h * ROW2 + j], w[j]);
    }
}

// hidden activations, packed over h; result pre-duplicated (v,v) per h.
__device__ __forceinline__ void mlp_hidden2(const float* __restrict__ edge_sc, int e,
                                            const float* __restrict__ sW1,
                                            u64* __restrict__ hkp)
{
    float sv[EB];
    const float4* sp = (const float4*)(edge_sc + (size_t)e * EB);
#pragma unroll
    for (int i = 0; i < EB / 4; i++) {
        float4 v = sp[i];
        sv[i * 4 + 0] = v.x; sv[i * 4 + 1] = v.y;
        sv[i * 4 + 2] = v.z; sv[i * 4 + 3] = v.w;
    }
    u64 acc[HID / 2];
#pragma unroll
    for (int j = 0; j < HID / 2; j++) acc[j] = 0ull;
#pragma unroll
    for (int i = 0; i < EB; i++) {
        u64 s2 = pk(sv[i], sv[i]);
        const u64* w1p = (const u64*)(sW1 + i * HID);
#pragma unroll
        for (int j = 0; j < HID / 2; j++)
            acc[j] = fma2(s2, w1p[j], acc[j]);
    }
#pragma unroll
    for (int j = 0; j < HID / 2; j++) {
        float a, b;
        upk(acc[j], a, b);
        a *= 0.25f; b *= 0.25f;
        a = (a / (1.0f + __expf(-a))) * INV_SQRT32;
        b = (b / (1.0f + __expf(-b))) * INV_SQRT32;
        hkp[2 * j + 0] = pk(a, a);
        hkp[2 * j + 1] = pk(b, b);
    }
}

__device__ __forceinline__ void load_node(const float* __restrict__ x,
                                          float* __restrict__ xs,
                                          float (*__restrict__ xv)[3])
{
    const float4* xp = (const float4*)x;
#pragma unroll
    for (int i = 0; i < 4; i++) {
        float4 v = xp[i];
        xs[i * 4 + 0] = v.x; xs[i * 4 + 1] = v.y;
        xs[i * 4 + 2] = v.z; xs[i * 4 + 3] = v.w;
    }
    float tmp[24];
#pragma unroll
    for (int i = 0; i < 6; i++) {
        float4 v = xp[4 + i];
        tmp[i * 4 + 0] = v.x; tmp[i * 4 + 1] = v.y;
        tmp[i * 4 + 2] = v.z; tmp[i * 4 + 3] = v.w;
    }
#pragma unroll
    for (int i = 0; i < M1; i++)
#pragma unroll
        for (int c = 0; c < 3; c++) xv[i][c] = tmp[i * 3 + c];
}

// ---------------------------------------------------------------------------
// Kernel 1: per-node q-tilde (wdot + norms folded), zero z and out.
// ---------------------------------------------------------------------------
__global__ void q_kernel(const float* __restrict__ node_ft,
                         const float* __restrict__ wqs,
                         const float* __restrict__ wqv,
                         const float* __restrict__ wds,
                         const float* __restrict__ wdv,
                         float* __restrict__ out, int N)
{
    int n = blockIdx.x * blockDim.x + threadIdx.x;
    if (n >= N) return;
    const float* x = node_ft + (size_t)n * NODE_DIM;

    float xs[M0];
#pragma unroll
    for (int i = 0; i < M0; i++) xs[i] = x[i];
    float xv[M1][3];
#pragma unroll
    for (int i = 0; i < M1; i++)
#pragma unroll
        for (int c = 0; c < 3; c++) xv[i][c] = x[M0 + i * 3 + c];

    float qs[Q0];
#pragma unroll
    for (int o = 0; o < Q0; o++) {
        float t = 0.f;
#pragma unroll
        for (int i = 0; i < M0; i++) t += xs[i] * wqs[i * Q0 + o];
        qs[o] = t * 0.25f;
    }
    float qv[Q1][3];
#pragma unroll
    for (int o = 0; o < Q1; o++)
#pragma unroll
        for (int c = 0; c < 3; c++) {
            float t = 0.f;
#pragma unroll
            for (int i = 0; i < M1; i++) t += xv[i][c] * wqv[i * Q1 + o];
            qv[o][c] = t * INV_SQRT8;
        }

#pragma unroll
    for (int j = 0; j < Q0; j++) {
        float t = 0.f;
#pragma unroll
        for (int i = 0; i < Q0; i++) t += qs[i] * wds[i * Q0 + j];
        g_qts[n * Q0 + j] = t * CS_FOLD;
    }
#pragma unroll
    for (int j = 0; j < Q1; j++)
#pragma unroll
        for (int c = 0; c < 3; c++) {
            float t = 0.f;
#pragma unroll
            for (int i = 0; i < Q1; i++) t += qv[i][c] * wdv[i * Q1 + j];
            g_qtv[n * 12 + j * 3 + c] = t * CV_FOLD;
        }

    g_z[n] = 0.f;
#pragma unroll
    for (int k = 0; k < OUT_DIM; k++) out[(size_t)n * OUT_DIM + k] = 0.f;
}

// ---------------------------------------------------------------------------
// Kernel 2 (pass 1): per-edge K tensor product + dot + exp + z accumulation.
// ---------------------------------------------------------------------------
__global__ void __launch_bounds__(256) pass1_kernel(
    const float* __restrict__ node_ft,
    const int* __restrict__ eidx,
    const float* __restrict__ edge_sh,
    const float* __restrict__ edge_sc,
    const float* __restrict__ W1g,
    const float* __restrict__ W2g,
    int E)
{
    extern __shared__ float sm[];
    float* sW1 = sm;               // [16*32]
    float* sW2 = sm + EB * HID;    // [32*320]
    for (int i = threadIdx.x; i < EB * HID; i += blockDim.x) sW1[i] = W1g[i];
    for (int i = threadIdx.x; i < HID * TPK; i += blockDim.x) sW2[i] = W2g[i];
    __syncthreads();

    int e = blockIdx.x * blockDim.x + threadIdx.x;
    if (e >= E) return;

    u64 hkp[HID];
    mlp_hidden2(edge_sc, e, sW1, hkp);

    int snd = eidx[e];
    float xs[M0];
    float xv[M1][3];
    load_node(node_ft + (size_t)snd * NODE_DIM, xs, xv);

    float4 sh = ((const float4*)edge_sh)[e];
    float sh0 = sh.x, shx = sh.y, shy = sh.z, shz = sh.w;

    float pvv[M1];
#pragma unroll
    for (int i = 0; i < M1; i++)
        pvv[i] = (xv[i][0] * shx + xv[i][1] * shy + xv[i][2] * shz) * INV_SQRT3;

    u64 ks2[Q0 / 2]  = {0, 0, 0, 0};      // packed over o
    u64 kvx2[Q1 / 2] = {0, 0};            // packed over o, x component
    u64 kvy2[Q1 / 2] = {0, 0};
    u64 kvz2[Q1 / 2] = {0, 0};

    // path1: ss -> scalar, [16,8] at 0
#pragma unroll 1
    for (int i = 0; i < M0; i++) {
        u64 w[4];
        weff2<TPK / 2, 4>(sW2 + i * Q0, hkp, w);
        float p = xs[i] * sh0;
        u64 p2 = pk(p, p);
#pragma unroll
        for (int j = 0; j < 4; j++) ks2[j] = fma2(p2, w[j], ks2[j]);
    }
    // path2: vv -> scalar, [8,8] at 128
#pragma unroll 1
    for (int i = 0; i < M1; i++) {
        u64 w[4];
        weff2<TPK / 2, 4>(sW2 + 128 + i * Q0, hkp, w);
        u64 p2 = pk(pvv[i], pvv[i]);
#pragma unroll
        for (int j = 0; j < 4; j++) ks2[j] = fma2(p2, w[j], ks2[j]);
    }
    // path3: sv -> vector, [16,4] at 192
#pragma unroll 1
    for (int i = 0; i < M0; i++) {
        u64 w[2];
        weff2<TPK / 2, 2>(sW2 + 192 + i * Q1, hkp, w);
        float p = xs[i];
        u64 t0 = pk(p * shx, p * shx), t1 = pk(p * shy, p * shy), t2 = pk(p * shz, p * shz);
#pragma unroll
        for (int j = 0; j < 2; j++) {
            kvx2[j] = fma2(t0, w[j], kvx2[j]);
            kvy2[j] = fma2(t1, w[j], kvy2[j]);
            kvz2[j] = fma2(t2, w[j], kvz2[j]);
        }
    }
    // path4: vs -> vector, [8,4] at 256
#pragma unroll 1
    for (int i = 0; i < M1; i++) {
        u64 w[2];
        weff2<TPK / 2, 2>(sW2 + 256 + i * Q1, hkp, w);
        float a0 = xv[i][0] * sh0, a1 = xv[i][1] * sh0, a2 = xv[i][2] * sh0;
        u64 t0 = pk(a0, a0), t1 = pk(a1, a1), t2 = pk(a2, a2);
#pragma unroll
        for (int j = 0; j < 2; j++) {
            kvx2[j] = fma2(t0, w[j], kvx2[j]);
            kvy2[j] = fma2(t1, w[j], kvy2[j]);
            kvz2[j] = fma2(t2, w[j], kvz2[j]);
        }
    }
    // path5: cross -> vector, [8,4] at 288
#pragma unroll 1
    for (int i = 0; i < M1; i++) {
        u64 w[2];
        weff2<TPK / 2, 2>(sW2 + 288 + i * Q1, hkp, w);
        float cx = (xv[i][1] * shz - xv[i][2] * shy) * INV_SQRT2;
        float cy = (xv[i][2] * shx - xv[i][0] * shz) * INV_SQRT2;
        float cz = (xv[i][0] * shy - xv[i][1] * shx) * INV_SQRT2;
        u64 t0 = pk(cx, cx), t1 = pk(cy, cy), t2 = pk(cz, cz);
#pragma unroll
        for (int j = 0; j < 2; j++) {
            kvx2[j] = fma2(t0, w[j], kvx2[j]);
            kvy2[j] = fma2(t1, w[j], kvy2[j]);
            kvz2[j] = fma2(t2, w[j], kvz2[j]);
        }
    }

    int rcv = eidx[E + e];
    const float* qts = g_qts + (size_t)rcv * Q0;
    const float* qtv = g_qtv + (size_t)rcv * 12;
    float dot = 0.f;
#pragma unroll
    for (int j = 0; j < Q0 / 2; j++) {
        float a, b;
        upk(ks2[j], a, b);
        dot += qts[2 * j] * a + qts[2 * j + 1] * b;
    }
#pragma unroll
    for (int j = 0; j < Q1 / 2; j++) {
        float x0, x1, y0, y1, z0, z1;
        upk(kvx2[j], x0, x1);
        upk(kvy2[j], y0, y1);
        upk(kvz2[j], z0, z1);
        int o = 2 * j;
        dot += qtv[o * 3 + 0] * x0 + qtv[o * 3 + 1] * y0 + qtv[o * 3 + 2] * z0;
        dot += qtv[(o + 1) * 3 + 0] * x1 + qtv[(o + 1) * 3 + 1] * y1 + qtv[(o + 1) * 3 + 2] * z1;
    }

    float ex = expf(dot);
    g_ex[e] = ex;
    atomicAdd(&g_z[rcv], ex);
}

// ---------------------------------------------------------------------------
// Kernel 3 (pass 2): per-edge V tensor product, softmax weight, scatter-add.
// ---------------------------------------------------------------------------
__global__ void __launch_bounds__(256) pass2_kernel(
    const float* __restrict__ node_ft,
    const int* __restrict__ eidx,
    const float* __restrict__ edge_sh,
    const float* __restrict__ edge_sc,
    const float* __restrict__ W1g,
    const float* __restrict__ W2g,
    float* __restrict__ out,
    int E)
{
    extern __shared__ float sm[];
    float* sW1 = sm;               // [16*32]
    float* sW2 = sm + EB * HID;    // [32*640]
    for (int i = threadIdx.x; i < EB * HID; i += blockDim.x) sW1[i] = W1g[i];
    for (int i = threadIdx.x; i < HID * TPV; i += blockDim.x) sW2[i] = W2g[i];
    __syncthreads();

    int e = blockIdx.x * blockDim.x + threadIdx.x;
    if (e >= E) return;

    u64 hkp[HID];
    mlp_hidden2(edge_sc, e, sW1, hkp);

    int snd = eidx[e];
    float xs[M0];
    float xv[M1][3];
    load_node(node_ft + (size_t)snd * NODE_DIM, xs, xv);

    float4 sh = ((const float4*)edge_sh)[e];
    float sh0 = sh.x, shx = sh.y, shy = sh.z, shz = sh.w;

    float pvv[M1];
#pragma unroll
    for (int i = 0; i < M1; i++)
        pvv[i] = (xv[i][0] * shx + xv[i][1] * shy + xv[i][2] * shz) * INV_SQRT3;

    u64 vs2[O0 / 2]  = {0, 0, 0, 0, 0, 0, 0, 0};
    u64 vvx2[O1 / 2] = {0, 0, 0, 0};
    u64 vvy2[O1 / 2] = {0, 0, 0, 0};
    u64 vvz2[O1 / 2] = {0, 0, 0, 0};

    // path1: ss -> scalar, [16,16] at 0
#pragma unroll 1
    for (int i = 0; i < M0; i++) {
        u64 w[8];
        weff2<TPV / 2, 8>(sW2 + i * O0, hkp, w);
        float p = xs[i] * sh0;
        u64 p2 = pk(p, p);
#pragma unroll
        for (int j = 0; j < 8; j++) vs2[j] = fma2(p2, w[j], vs2[j]);
    }
    // path2: vv -> scalar, [8,16] at 256
#pragma unroll 1
    for (int i = 0; i < M1; i++) {
        u64 w[8];
        weff2<TPV / 2, 8>(sW2 + 256 + i * O0, hkp, w);
        u64 p2 = pk(pvv[i], pvv[i]);
#pragma unroll
        for (int j = 0; j < 8; j++) vs2[j] = fma2(p2, w[j], vs2[j]);
    }
    // path3: sv -> vector, [16,8] at 384
#pragma unroll 1
    for (int i = 0; i < M0; i++) {
        u64 w[4];
        weff2<TPV / 2, 4>(sW2 + 384 + i * O1, hkp, w);
        float p = xs[i];
        u64 t0 = pk(p * shx, p * shx), t1 = pk(p * shy, p * shy), t2 = pk(p * shz, p * shz);
#pragma unroll
        for (int j = 0; j < 4; j++) {
            vvx2[j] = fma2(t0, w[j], vvx2[j]);
            vvy2[j] = fma2(t1, w[j], vvy2[j]);
            vvz2[j] = fma2(t2, w[j], vvz2[j]);
        }
    }
    // path4: vs -> vector, [8,8] at 512
#pragma unroll 1
    for (int i = 0; i < M1; i++) {
        u64 w[4];
        weff2<TPV / 2, 4>(sW2 + 512 + i * O1, hkp, w);
        float a0 = xv[i][0] * sh0, a1 = xv[i][1] * sh0, a2 = xv[i][2] * sh0;
        u64 t0 = pk(a0, a0), t1 = pk(a1, a1), t2 = pk(a2, a2);
#pragma unroll
        for (int j = 0; j < 4; j++) {
            vvx2[j] = fma2(t0, w[j], vvx2[j]);
            vvy2[j] = fma2(t1, w[j], vvy2[j]);
            vvz2[j] = fma2(t2, w[j], vvz2[j]);
        }
    }
    // path5: cross -> vector, [8,8] at 576
#pragma unroll 1
    for (int i = 0; i < M1; i++) {
        u64 w[4];
        weff2<TPV / 2, 4>(sW2 + 576 + i * O1, hkp, w);
        float cx = (xv[i][1] * shz - xv[i][2] * shy) * INV_SQRT2;
        float cy = (xv[i][2] * shx - xv[i][0] * shz) * INV_SQRT2;
        float cz = (xv[i][0] * shy - xv[i][1] * shx) * INV_SQRT2;
        u64 t0 = pk(cx, cx), t1 = pk(cy, cy), t2 = pk(cz, cz);
#pragma unroll
        for (int j = 0; j < 4; j++) {
            vvx2[j] = fma2(t0, w[j], vvx2[j]);
            vvy2[j] = fma2(t1, w[j], vvy2[j]);
            vvz2[j] = fma2(t2, w[j], vvz2[j]);
        }
    }

    int rcv = eidx[E + e];
    float a = sqrtf(g_ex[e] / g_z[rcv]);
    float cs = a * INV_SQRT24;
    float cv = a * INV_SQRT32;
    float* op = out + (size_t)rcv * OUT_DIM;
#pragma unroll
    for (int j = 0; j < O0 / 2; j++) {
        float x0, x1;
        upk(vs2[j], x0, x1);
        atomicAdd(op + 2 * j + 0, cs * x0);
        atomicAdd(op + 2 * j + 1, cs * x1);
    }
#pragma unroll
    for (int j = 0; j < O1 / 2; j++) {
        float x0, x1, y0, y1, z0, z1;
        upk(vvx2[j], x0, x1);
        upk(vvy2[j], y0, y1);
        upk(vvz2[j], z0, z1);
        int o = 2 * j;
        atomicAdd(op + O0 + o * 3 + 0, cv * x0);
        atomicAdd(op + O0 + o * 3 + 1, cv * y0);
        atomicAdd(op + O0 + o * 3 + 2, cv * z0);
        atomicAdd(op + O0 + (o + 1) * 3 + 0, cv * x1);
        atomicAdd(op + O0 + (o + 1) * 3 + 1, cv * y1);
        atomicAdd(op + O0 + (o + 1) * 3 + 2, cv * z1);
    }
}

// ---------------------------------------------------------------------------
extern "C" void kernel_launch(void* const* d_in, const int* in_sizes, int n_in,
                              void* d_out, int out_size)
{
    const float* node_ft = (const float*)d_in[0];
    const int* eidx      = (const int*)d_in[1];
    const float* edge_sh = (const float*)d_in[2];
    const float* edge_sc = (const float*)d_in[3];
    const float* wqs     = (const float*)d_in[4];
    const float* wqv     = (const float*)d_in[5];
    const float* fck_w1  = (const float*)d_in[6];
    const float* fck_w2  = (const float*)d_in[7];
    const float* fcv_w1  = (const float*)d_in[8];
    const float* fcv_w2  = (const float*)d_in[9];
    const float* wds     = (const float*)d_in[10];
    const float* wdv     = (const float*)d_in[11];
    float* out = (float*)d_out;

    int N = in_sizes[0] / NODE_DIM;
    int E = in_sizes[1] / 2;

    size_t smem1 = (size_t)(EB * HID + HID * TPK) * sizeof(float);  // 43008
    size_t smem2 = (size_t)(EB * HID + HID * TPV) * sizeof(float);  // 83968
    cudaFuncSetAttribute(pass1_kernel, cudaFuncAttributeMaxDynamicSharedMemorySize, (int)smem1);
    cudaFuncSetAttribute(pass2_kernel, cudaFuncAttributeMaxDynamicSharedMemorySize, (int)smem2);

    q_kernel<<<(N + 127) / 128, 128>>>(node_ft, wqs, wqv, wds, wdv, out, N);
    pass1_kernel<<<(E + 255) / 256, 256, smem1>>>(node_ft, eidx, edge_sh, edge_sc,
                                                  fck_w1, fck_w2, E);
    pass2_kernel<<<(E + 255) / 256, 256, smem2>>>(node_ft, eidx, edge_sh, edge_sc,
                                                  fcv_w2 ? fcv_w1 : fcv_w1, fcv_w2, out, E);
}